// round 11
// baseline (speedup 1.0000x reference)
#include <cuda_runtime.h>
#include <cuda_fp16.h>
#include <cstdint>

#define EPS 1e-5f
#define NTHREADS 320     // 8 consumer warps + 2 producer warps
#define NCHUNK 16        // K chunks of 16
#define STAGES 4

__device__ __half g_Wh[384 * 256];
__device__ float g_bnsc[384];
__device__ float g_bnsh[384];

// smem: 4-stage rings, 4 KB per stage each
#define OFF_A   0u       // A fp16: 128 rows x 32B (swzA16)
#define OFF_BC  16384u   // B fp16 c: 16 rows x 256B (swzB)
#define OFF_BX  32768u   // B fp16 x: 16 rows x 256B
#define SMEM_TOTAL 49152

__device__ __forceinline__ uint32_t swzA16(uint32_t o) { return o ^ ((o >> 3) & 0x10); }
__device__ __forceinline__ uint32_t swzB(uint32_t o)   { return o ^ ((o >> 4) & 0x70); }

__device__ __forceinline__ uint32_t s2u(const void* p) {
    uint32_t a;
    asm("{ .reg .u64 t; cvta.to.shared.u64 t, %1; cvt.u32.u64 %0, t; }" : "=r"(a) : "l"(p));
    return a;
}
__device__ __forceinline__ void bar_sync(int id) {
    asm volatile("bar.sync %0, %1;" :: "r"(id), "r"(NTHREADS) : "memory");
}
__device__ __forceinline__ void bar_arrive(int id) {
    asm volatile("bar.arrive %0, %1;" :: "r"(id), "r"(NTHREADS) : "memory");
}
__device__ __forceinline__ void ldsm_x4(uint32_t* r, uint32_t a) {
    asm volatile("ldmatrix.sync.aligned.m8n8.x4.shared.b16 {%0,%1,%2,%3}, [%4];"
                 : "=r"(r[0]), "=r"(r[1]), "=r"(r[2]), "=r"(r[3]) : "r"(a));
}
__device__ __forceinline__ void ldsm_x4t(uint32_t* r, uint32_t a) {
    asm volatile("ldmatrix.sync.aligned.m8n8.x4.trans.shared.b16 {%0,%1,%2,%3}, [%4];"
                 : "=r"(r[0]), "=r"(r[1]), "=r"(r[2]), "=r"(r[3]) : "r"(a));
}
__device__ __forceinline__ void mma16816(float* d, const uint32_t* a, const uint32_t* b) {
    asm volatile("mma.sync.aligned.m16n8k16.row.col.f32.f16.f16.f32 "
                 "{%0,%1,%2,%3}, {%4,%5,%6,%7}, {%8,%9}, {%0,%1,%2,%3};"
                 : "+f"(d[0]), "+f"(d[1]), "+f"(d[2]), "+f"(d[3])
                 : "r"(a[0]), "r"(a[1]), "r"(a[2]), "r"(a[3]), "r"(b[0]), "r"(b[1]));
}
__device__ __forceinline__ void cpa16(uint32_t dst, const void* src) {
    asm volatile("cp.async.cg.shared.global [%0], [%1], 16;" :: "r"(dst), "l"(src));
}

// ---------------- prep: W fp32 -> fp16, fold BN ----------------
__global__ void prep_kernel(const float* __restrict__ Wq, const float* __restrict__ Wv,
                            const float* __restrict__ Wk,
                            const float* __restrict__ qg, const float* __restrict__ qb,
                            const float* __restrict__ qm, const float* __restrict__ qv,
                            const float* __restrict__ vg, const float* __restrict__ vb,
                            const float* __restrict__ vm, const float* __restrict__ vv)
{
    int idx = blockIdx.x * blockDim.x + threadIdx.x;
    int stride = gridDim.x * blockDim.x;
    for (int i = idx; i < 384 * 256; i += stride) {
        int r = i >> 8, k = i & 255;
        float w = (r < 64) ? Wq[(r << 8) | k]
                : (r < 320) ? Wv[((r - 64) << 8) | k]
                            : Wk[((r - 320) << 8) | k];
        g_Wh[i] = __float2half_rn(w);
    }
    if (idx < 384) {
        float sc = 1.f, sh = 0.f;
        if (idx < 320) {
            float g, b, m, v;
            if (idx < 64) { g = qg[idx]; b = qb[idx]; m = qm[idx]; v = qv[idx]; }
            else { g = vg[idx-64]; b = vb[idx-64]; m = vm[idx-64]; v = vv[idx-64]; }
            sc = g * rsqrtf(v + EPS);
            sh = b - m * sc;
        }
        g_bnsc[idx] = sc; g_bnsh[idx] = sh;
    }
}

// ---------------- main: warp-specialized fp16 HMMA GEMM ----------------
__global__ __launch_bounds__(NTHREADS, 2)
void main_kernel(const float* __restrict__ x, const float* __restrict__ c,
                 float* __restrict__ out)
{
    extern __shared__ char smem[];
    const uint32_t sb = s2u(smem);
    const int tid = threadIdx.x, wid = tid >> 5, lane = tid & 31;
    const int bid = blockIdx.x;
    const int mblk = bid % 3;                        // ch blocks 0-127 / 128-255 / 256-383
    const int tile = bid / 3;
    const int b = tile >> 5, pxb = (tile & 31) << 7;
    const int ch0 = mblk << 7;
    const bool needX = (mblk == 0);

    if (wid >= 8) {
        // ================= producer warps (64 threads) =================
        const int pt = tid - 256;                    // 0..63
        for (int k = 0; k < NCHUNK; k++) {
            const int s = k & 3;
            const int kc = k << 4;
            if (k >= STAGES) bar_sync(4 + s);        // wait empty[s]
            // ---- A: 256 x 16B granules via cp.async ----
            const uint32_t abuf = sb + OFF_A + (uint32_t)(s << 12);
            #pragma unroll
            for (int j = 0; j < 4; j++) {
                int idx = (pt << 2) + j;
                int r = idx >> 1, u = idx & 1;
                cpa16(abuf + swzA16((uint32_t)((r << 5) + (u << 4))),
                      g_Wh + ((ch0 + r) << 8) + kc + (u << 3));
            }
            asm volatile("cp.async.commit_group;");
            // ---- B c: LDG fp32 -> cvt -> STS fp16 ----
            #pragma unroll
            for (int j = 0; j < 8; j++) {
                int idx = (pt << 3) + j;
                int kk = idx >> 5, p = idx & 31;
                float4 v = *(const float4*)(c + (size_t)((b << 8) + kc + kk) * 4096
                                              + pxb + (p << 2));
                __half2 h0 = __floats2half2_rn(v.x, v.y);
                __half2 h1 = __floats2half2_rn(v.z, v.w);
                *(uint2*)(smem + OFF_BC + (s << 12)
                              + swzB((uint32_t)((kk << 8) + (p << 3)))) =
                    make_uint2(*(uint32_t*)&h0, *(uint32_t*)&h1);
            }
            if (needX) {
                #pragma unroll
                for (int j = 0; j < 8; j++) {
                    int idx = (pt << 3) + j;
                    int kk = idx >> 5, p = idx & 31;
                    float4 v = *(const float4*)(x + (size_t)((b << 8) + kc + kk) * 4096
                                                  + pxb + (p << 2));
                    __half2 h0 = __floats2half2_rn(v.x, v.y);
                    __half2 h1 = __floats2half2_rn(v.z, v.w);
                    *(uint2*)(smem + OFF_BX + (s << 12)
                                  + swzB((uint32_t)((kk << 8) + (p << 3)))) =
                        make_uint2(*(uint32_t*)&h0, *(uint32_t*)&h1);
                }
            }
            asm volatile("cp.async.wait_group 0;");  // A[s] landed
            bar_arrive(s);                           // publish full[s]
        }
        return;                                      // producers exit; epilogue is smem-free
    }

    // ================= consumer warps (256 threads) =================
    const int mw = wid >> 1, nw = wid & 1;           // warp grid 4(M) x 2(N)
    float d[2][8][4];
    #pragma unroll
    for (int mt = 0; mt < 2; mt++)
        #pragma unroll
        for (int nt = 0; nt < 8; nt++)
            d[mt][nt][0] = d[mt][nt][1] = d[mt][nt][2] = d[mt][nt][3] = 0.f;

    // q channels (block0, mw<2) reduce over x; everything else over c
    const uint32_t offB = (mblk == 0 && mw < 2) ? OFF_BX : OFF_BC;

    for (int k = 0; k < NCHUNK; k++) {
        const int s = k & 3;
        bar_sync(s);                                 // wait full[s]
        const uint32_t abuf = sb + OFF_A + (uint32_t)(s << 12);
        const uint32_t bbuf = sb + offB + (uint32_t)(s << 12);
        uint32_t a[2][4], bf[8][2];
        #pragma unroll
        for (int mt = 0; mt < 2; mt++) {
            int row = (mw << 5) + (mt << 4) + (lane & 15);
            int kb  = (lane >> 4) << 4;
            ldsm_x4(a[mt], abuf + swzA16((uint32_t)((row << 5) + kb)));
        }
        #pragma unroll
        for (int p = 0; p < 4; p++) {
            int krow = lane & 15;
            int ncol = (nw << 6) + (p << 4) + ((lane >> 4) << 3);
            uint32_t r[4];
            ldsm_x4t(r, bbuf + swzB((uint32_t)((krow << 8) + (ncol << 1))));
            bf[2*p][0] = r[0]; bf[2*p][1] = r[1];
            bf[2*p+1][0] = r[2]; bf[2*p+1][1] = r[3];
        }
        #pragma unroll
        for (int mt = 0; mt < 2; mt++)
            #pragma unroll
            for (int nt = 0; nt < 8; nt++)
                mma16816(d[mt][nt], a[mt], bf[nt]);
        bar_arrive(4 + s);                           // release empty[s]
    }

    // ================= epilogue (consumers only, no smem) =================
    const int g = lane >> 2, cc = lane & 3;
    const bool isK = (mblk == 2 && mw >= 2);         // channels 320-383

    #pragma unroll
    for (int mt = 0; mt < 2; mt++) {
        const int chA = ch0 + (mw << 5) + (mt << 4) + g;
        float* oA = out + ((size_t)b * 384 + chA) * 4096 + pxb + (nw << 6);
        float* oB = oA + (size_t)8 * 4096;
        if (!isK) {
            float s0 = g_bnsc[chA],     h0 = g_bnsh[chA];
            float s1 = g_bnsc[chA + 8], h1 = g_bnsh[chA + 8];
            #pragma unroll
            for (int nt = 0; nt < 8; nt++) {
                int col = (nt << 3) + (cc << 1);
                *(float2*)(oA + col) = make_float2(fmaf(d[mt][nt][0], s0, h0),
                                                   fmaf(d[mt][nt][1], s0, h0));
                *(float2*)(oB + col) = make_float2(fmaf(d[mt][nt][2], s1, h1),
                                                   fmaf(d[mt][nt][3], s1, h1));
            }
        } else {
            // softmax over this warp's 64 cols = one full W row (4-thread quad per row)
            float mx0 = -3.4e38f, mx1 = -3.4e38f;
            #pragma unroll
            for (int nt = 0; nt < 8; nt++) {
                mx0 = fmaxf(mx0, fmaxf(d[mt][nt][0], d[mt][nt][1]));
                mx1 = fmaxf(mx1, fmaxf(d[mt][nt][2], d[mt][nt][3]));
            }
            mx0 = fmaxf(mx0, __shfl_xor_sync(0xffffffffu, mx0, 1));
            mx0 = fmaxf(mx0, __shfl_xor_sync(0xffffffffu, mx0, 2));
            mx1 = fmaxf(mx1, __shfl_xor_sync(0xffffffffu, mx1, 1));
            mx1 = fmaxf(mx1, __shfl_xor_sync(0xffffffffu, mx1, 2));
            float s0 = 0.f, s1 = 0.f;
            #pragma unroll
            for (int nt = 0; nt < 8; nt++) {
                d[mt][nt][0] = __expf(d[mt][nt][0] - mx0); s0 += d[mt][nt][0];
                d[mt][nt][1] = __expf(d[mt][nt][1] - mx0); s0 += d[mt][nt][1];
                d[mt][nt][2] = __expf(d[mt][nt][2] - mx1); s1 += d[mt][nt][2];
                d[mt][nt][3] = __expf(d[mt][nt][3] - mx1); s1 += d[mt][nt][3];
            }
            s0 += __shfl_xor_sync(0xffffffffu, s0, 1);
            s0 += __shfl_xor_sync(0xffffffffu, s0, 2);
            s1 += __shfl_xor_sync(0xffffffffu, s1, 1);
            s1 += __shfl_xor_sync(0xffffffffu, s1, 2);
            float i0 = __frcp_rn(s0), i1 = __frcp_rn(s1);
            #pragma unroll
            for (int nt = 0; nt < 8; nt++) {
                int col = (nt << 3) + (cc << 1);
                *(float2*)(oA + col) = make_float2(d[mt][nt][0] * i0, d[mt][nt][1] * i0);
                *(float2*)(oB + col) = make_float2(d[mt][nt][2] * i1, d[mt][nt][3] * i1);
            }
        }
    }
}

extern "C" void kernel_launch(void* const* d_in, const int* in_sizes, int n_in,
                              void* d_out, int out_size)
{
    const float* x = (const float*)d_in[0];
    const float* c = (const float*)d_in[1];
    prep_kernel<<<96, 256>>>((const float*)d_in[2], (const float*)d_in[3],
                             (const float*)d_in[4], (const float*)d_in[5],
                             (const float*)d_in[6], (const float*)d_in[7],
                             (const float*)d_in[8], (const float*)d_in[9],
                             (const float*)d_in[10], (const float*)d_in[11],
                             (const float*)d_in[12]);
    cudaFuncSetAttribute(main_kernel, cudaFuncAttributeMaxDynamicSharedMemorySize, SMEM_TOTAL);
    main_kernel<<<3072, NTHREADS, SMEM_TOTAL>>>(x, c, (float*)d_out);
}

// round 12
// speedup vs baseline: 1.7587x; 1.7587x over previous
#include <cuda_runtime.h>
#include <cuda_fp16.h>
#include <cstdint>

#define EPS 1e-5f

__device__ __half g_Wh[384 * 256];
__device__ float g_bnsc[384];
__device__ float g_bnsh[384];

// ---- smem map (bytes). A resident = 64 KB at offset 0 for both variants ----
// variant C (mblk 1,2; K-chunk 32): B16c 2x8KB @65536, staging c 2x16KB @81920
// variant M (mblk 0;   K-chunk 16): B16c 2x4KB @65536, B16x 2x4KB @73728,
//                                    stg c 2x8KB @81920, stg x 2x8KB @98304
#define OFF_A     0u
#define OFF_BC    65536u
#define OFF_BX_M  73728u
#define OFF_SC    81920u
#define OFF_SX_M  98304u
#define SMEM_TOTAL 114688   // 112 KB -> 2 CTAs/SM

__device__ __forceinline__ uint32_t swzA32(uint32_t o) { return o ^ ((o >> 3) & 0x30); } // 64B rows
__device__ __forceinline__ uint32_t swzA16(uint32_t o) { return o ^ ((o >> 3) & 0x10); } // 32B rows
__device__ __forceinline__ uint32_t swzB(uint32_t o)   { return o ^ ((o >> 4) & 0x70); } // 256B rows

__device__ __forceinline__ uint32_t s2u(const void* p) {
    uint32_t a;
    asm("{ .reg .u64 t; cvta.to.shared.u64 t, %1; cvt.u32.u64 %0, t; }" : "=r"(a) : "l"(p));
    return a;
}
__device__ __forceinline__ void ldsm_x4(uint32_t* r, uint32_t a) {
    asm volatile("ldmatrix.sync.aligned.m8n8.x4.shared.b16 {%0,%1,%2,%3}, [%4];"
                 : "=r"(r[0]), "=r"(r[1]), "=r"(r[2]), "=r"(r[3]) : "r"(a));
}
__device__ __forceinline__ void ldsm_x4t(uint32_t* r, uint32_t a) {
    asm volatile("ldmatrix.sync.aligned.m8n8.x4.trans.shared.b16 {%0,%1,%2,%3}, [%4];"
                 : "=r"(r[0]), "=r"(r[1]), "=r"(r[2]), "=r"(r[3]) : "r"(a));
}
__device__ __forceinline__ void mma16816(float* d, const uint32_t* a, const uint32_t* b) {
    asm volatile("mma.sync.aligned.m16n8k16.row.col.f32.f16.f16.f32 "
                 "{%0,%1,%2,%3}, {%4,%5,%6,%7}, {%8,%9}, {%0,%1,%2,%3};"
                 : "+f"(d[0]), "+f"(d[1]), "+f"(d[2]), "+f"(d[3])
                 : "r"(a[0]), "r"(a[1]), "r"(a[2]), "r"(a[3]), "r"(b[0]), "r"(b[1]));
}
__device__ __forceinline__ void cpa16(uint32_t dst, const void* src) {
    asm volatile("cp.async.cg.shared.global [%0], [%1], 16;" :: "r"(dst), "l"(src));
}
__device__ __forceinline__ void cpa_commit() { asm volatile("cp.async.commit_group;"); }
__device__ __forceinline__ void cpa_wait0()  { asm volatile("cp.async.wait_group 0;"); }

// ---------------- prep: W fp32 -> fp16, fold BN ----------------
__global__ void prep_kernel(const float* __restrict__ Wq, const float* __restrict__ Wv,
                            const float* __restrict__ Wk,
                            const float* __restrict__ qg, const float* __restrict__ qb,
                            const float* __restrict__ qm, const float* __restrict__ qv,
                            const float* __restrict__ vg, const float* __restrict__ vb,
                            const float* __restrict__ vm, const float* __restrict__ vv)
{
    int idx = blockIdx.x * blockDim.x + threadIdx.x;
    int stride = gridDim.x * blockDim.x;
    for (int i = idx; i < 384 * 256; i += stride) {
        int r = i >> 8, k = i & 255;
        float w = (r < 64) ? Wq[(r << 8) | k]
                : (r < 320) ? Wv[((r - 64) << 8) | k]
                            : Wk[((r - 320) << 8) | k];
        g_Wh[i] = __float2half_rn(w);
    }
    if (idx < 384) {
        float sc = 1.f, sh = 0.f;
        if (idx < 320) {
            float g, b, m, v;
            if (idx < 64) { g = qg[idx]; b = qb[idx]; m = qm[idx]; v = qv[idx]; }
            else { g = vg[idx-64]; b = vb[idx-64]; m = vm[idx-64]; v = vv[idx-64]; }
            sc = g * rsqrtf(v + EPS);
            sh = b - m * sc;
        }
        g_bnsc[idx] = sc; g_bnsh[idx] = sh;
    }
}

// ---------------- shared epilogue (register-only + gmem) ----------------
__device__ __forceinline__ void epilogue_store(
    float d[2][8][4], float* __restrict__ out,
    int b, int pxb, int ch0, int mw, int nw, int lane, bool isK)
{
    const int g = lane >> 2, cc = lane & 3;
    #pragma unroll
    for (int mt = 0; mt < 2; mt++) {
        const int chA = ch0 + (mw << 5) + (mt << 4) + g;
        float* oA = out + ((size_t)b * 384 + chA) * 4096 + pxb + (nw << 6);
        float* oB = oA + (size_t)8 * 4096;
        if (!isK) {
            float s0 = g_bnsc[chA],     h0 = g_bnsh[chA];
            float s1 = g_bnsc[chA + 8], h1 = g_bnsh[chA + 8];
            #pragma unroll
            for (int nt = 0; nt < 8; nt++) {
                int col = (nt << 3) + (cc << 1);
                *(float2*)(oA + col) = make_float2(fmaf(d[mt][nt][0], s0, h0),
                                                   fmaf(d[mt][nt][1], s0, h0));
                *(float2*)(oB + col) = make_float2(fmaf(d[mt][nt][2], s1, h1),
                                                   fmaf(d[mt][nt][3], s1, h1));
            }
        } else {
            float mx0 = -3.4e38f, mx1 = -3.4e38f;
            #pragma unroll
            for (int nt = 0; nt < 8; nt++) {
                mx0 = fmaxf(mx0, fmaxf(d[mt][nt][0], d[mt][nt][1]));
                mx1 = fmaxf(mx1, fmaxf(d[mt][nt][2], d[mt][nt][3]));
            }
            mx0 = fmaxf(mx0, __shfl_xor_sync(0xffffffffu, mx0, 1));
            mx0 = fmaxf(mx0, __shfl_xor_sync(0xffffffffu, mx0, 2));
            mx1 = fmaxf(mx1, __shfl_xor_sync(0xffffffffu, mx1, 1));
            mx1 = fmaxf(mx1, __shfl_xor_sync(0xffffffffu, mx1, 2));
            float s0 = 0.f, s1 = 0.f;
            #pragma unroll
            for (int nt = 0; nt < 8; nt++) {
                d[mt][nt][0] = __expf(d[mt][nt][0] - mx0); s0 += d[mt][nt][0];
                d[mt][nt][1] = __expf(d[mt][nt][1] - mx0); s0 += d[mt][nt][1];
                d[mt][nt][2] = __expf(d[mt][nt][2] - mx1); s1 += d[mt][nt][2];
                d[mt][nt][3] = __expf(d[mt][nt][3] - mx1); s1 += d[mt][nt][3];
            }
            s0 += __shfl_xor_sync(0xffffffffu, s0, 1);
            s0 += __shfl_xor_sync(0xffffffffu, s0, 2);
            s1 += __shfl_xor_sync(0xffffffffu, s1, 1);
            s1 += __shfl_xor_sync(0xffffffffu, s1, 2);
            float i0 = __frcp_rn(s0), i1 = __frcp_rn(s1);
            #pragma unroll
            for (int nt = 0; nt < 8; nt++) {
                int col = (nt << 3) + (cc << 1);
                *(float2*)(oA + col) = make_float2(d[mt][nt][0] * i0, d[mt][nt][1] * i0);
                *(float2*)(oB + col) = make_float2(d[mt][nt][2] * i1, d[mt][nt][3] * i1);
            }
        }
    }
}

// ---------------- main: persistent, resident-A, pipelined HMMA ----------------
__global__ __launch_bounds__(256, 2)
void main_kernel(const float* __restrict__ x, const float* __restrict__ c,
                 float* __restrict__ out)
{
    extern __shared__ char smem[];
    const uint32_t sb = s2u(smem);
    const int tid = threadIdx.x, wid = tid >> 5, lane = tid & 31;
    const int mw = wid >> 1, nw = wid & 1;            // warp grid 4(M) x 2(N)
    const int cta = blockIdx.x;

    int mblk, r, n;
    if (cta < 120)      { mblk = 0; r = cta;       n = 120; }
    else if (cta < 212) { mblk = 1; r = cta - 120; n = 92;  }
    else                { mblk = 2; r = cta - 212; n = 92;  }
    const int t0 = (r * 1024) / n, t1 = ((r + 1) * 1024) / n;
    const int ch0 = mblk << 7;

    if (mblk != 0) {
        // ================= variant C: c-only, K-chunk 32 =================
        // resident A: 8 chunks x (128 rows x 64B, swzA32)
        #pragma unroll
        for (int i = 0; i < 16; i++) {
            int idx = tid + (i << 8);
            int ck = idx >> 9, j = idx & 511, rr = j >> 2, u = j & 3;
            cpa16(sb + (uint32_t)(ck << 13) + swzA32((uint32_t)((rr << 6) + (u << 4))),
                  g_Wh + ((ch0 + rr) << 8) + (ck << 5) + (u << 3));
        }
        cpa_commit();

        auto issueB = [&](int t, int ck) {
            int bb = t >> 5, pxb = (t & 31) << 7;
            const uint32_t ssel = OFF_SC + (uint32_t)((ck & 1) << 14);
            #pragma unroll
            for (int i = 0; i < 4; i++) {
                int idx = tid + (i << 8);
                int kk = idx >> 5, p = idx & 31;
                cpa16(sb + ssel + (uint32_t)((kk << 9) + (p << 4)),
                      c + (size_t)((bb << 8) + (ck << 5) + kk) * 4096 + pxb + (p << 2));
            }
            cpa_commit();
        };

        if (t0 < t1) issueB(t0, 0);
        for (int t = t0; t < t1; t++) {
            float d[2][8][4];
            #pragma unroll
            for (int mt = 0; mt < 2; mt++)
                #pragma unroll
                for (int nt = 0; nt < 8; nt++)
                    d[mt][nt][0] = d[mt][nt][1] = d[mt][nt][2] = d[mt][nt][3] = 0.f;

            for (int ck = 0; ck < 8; ck++) {
                cpa_wait0();
                __syncthreads();
                if (ck < 7) issueB(t, ck + 1);
                else if (t + 1 < t1) issueB(t + 1, 0);
                // convert staging[ck&1] -> B16[ck&1]
                const uint32_t ssel = OFF_SC + (uint32_t)((ck & 1) << 14);
                const uint32_t bsel = OFF_BC + (uint32_t)((ck & 1) << 13);
                #pragma unroll
                for (int i = 0; i < 4; i++) {
                    int idx = tid + (i << 8);
                    int kk = idx >> 5, p = idx & 31;
                    float4 v = *(const float4*)(smem + ssel + (kk << 9) + (p << 4));
                    __half2 h0 = __floats2half2_rn(v.x, v.y);
                    __half2 h1 = __floats2half2_rn(v.z, v.w);
                    *(uint2*)(smem + bsel + swzB((uint32_t)((kk << 8) + (p << 3)))) =
                        make_uint2(*(uint32_t*)&h0, *(uint32_t*)&h1);
                }
                __syncthreads();

                const uint32_t abuf = sb + (uint32_t)(ck << 13);
                const uint32_t bbuf = sb + OFF_BC + (uint32_t)((ck & 1) << 13);
                #pragma unroll
                for (int ks = 0; ks < 2; ks++) {
                    uint32_t a[2][4], bf[8][2];
                    #pragma unroll
                    for (int mt = 0; mt < 2; mt++) {
                        int row = (mw << 5) + (mt << 4) + (lane & 15);
                        int kb  = (ks << 5) + ((lane >> 4) << 4);
                        ldsm_x4(a[mt], abuf + swzA32((uint32_t)((row << 6) + kb)));
                    }
                    #pragma unroll
                    for (int p = 0; p < 4; p++) {
                        int krow = (ks << 4) + (lane & 15);
                        int ncol = (nw << 6) + (p << 4) + ((lane >> 4) << 3);
                        uint32_t rr[4];
                        ldsm_x4t(rr, bbuf + swzB((uint32_t)((krow << 8) + (ncol << 1))));
                        bf[2*p][0] = rr[0]; bf[2*p][1] = rr[1];
                        bf[2*p+1][0] = rr[2]; bf[2*p+1][1] = rr[3];
                    }
                    #pragma unroll
                    for (int mt = 0; mt < 2; mt++)
                        #pragma unroll
                        for (int nt = 0; nt < 8; nt++)
                            mma16816(d[mt][nt], a[mt], bf[nt]);
                }
            }
            epilogue_store(d, out, t >> 5, (t & 31) << 7, ch0, mw, nw, lane,
                           (mblk == 2 && mw >= 2));
        }
    } else {
        // ================= variant M: q+v mixed (x and c), K-chunk 16 =================
        // resident A: 16 chunks x (128 rows x 32B, swzA16)
        #pragma unroll
        for (int i = 0; i < 16; i++) {
            int idx = tid + (i << 8);
            int ck = idx >> 8, j = idx & 255, rr = j >> 1, u = j & 1;
            cpa16(sb + (uint32_t)(ck << 12) + swzA16((uint32_t)((rr << 5) + (u << 4))),
                  g_Wh + (rr << 8) + (ck << 4) + (u << 3));
        }
        cpa_commit();

        auto issueB = [&](int t, int ck) {
            int bb = t >> 5, pxb = (t & 31) << 7;
            const uint32_t sc = OFF_SC   + (uint32_t)((ck & 1) << 13);
            const uint32_t sx = OFF_SX_M + (uint32_t)((ck & 1) << 13);
            #pragma unroll
            for (int i = 0; i < 2; i++) {
                int idx = tid + (i << 8);
                int kk = idx >> 5, p = idx & 31;
                size_t go = (size_t)((bb << 8) + (ck << 4) + kk) * 4096 + pxb + (p << 2);
                uint32_t so = (uint32_t)((kk << 9) + (p << 4));
                cpa16(sb + sc + so, c + go);
                cpa16(sb + sx + so, x + go);
            }
            cpa_commit();
        };

        // q channels (mw<2) reduce over x; v channels over c
        const uint32_t offB = (mw < 2) ? OFF_BX_M : OFF_BC;

        if (t0 < t1) issueB(t0, 0);
        for (int t = t0; t < t1; t++) {
            float d[2][8][4];
            #pragma unroll
            for (int mt = 0; mt < 2; mt++)
                #pragma unroll
                for (int nt = 0; nt < 8; nt++)
                    d[mt][nt][0] = d[mt][nt][1] = d[mt][nt][2] = d[mt][nt][3] = 0.f;

            for (int ck = 0; ck < 16; ck++) {
                cpa_wait0();
                __syncthreads();
                if (ck < 15) issueB(t, ck + 1);
                else if (t + 1 < t1) issueB(t + 1, 0);
                const uint32_t scm = OFF_SC   + (uint32_t)((ck & 1) << 13);
                const uint32_t sxm = OFF_SX_M + (uint32_t)((ck & 1) << 13);
                const uint32_t bcm = OFF_BC   + (uint32_t)((ck & 1) << 12);
                const uint32_t bxm = OFF_BX_M + (uint32_t)((ck & 1) << 12);
                #pragma unroll
                for (int i = 0; i < 2; i++) {
                    int idx = tid + (i << 8);
                    int kk = idx >> 5, p = idx & 31;
                    uint32_t so = (uint32_t)((kk << 9) + (p << 4));
                    uint32_t bo = swzB((uint32_t)((kk << 8) + (p << 3)));
                    float4 v = *(const float4*)(smem + scm + so);
                    __half2 h0 = __floats2half2_rn(v.x, v.y);
                    __half2 h1 = __floats2half2_rn(v.z, v.w);
                    *(uint2*)(smem + bcm + bo) = make_uint2(*(uint32_t*)&h0, *(uint32_t*)&h1);
                    v = *(const float4*)(smem + sxm + so);
                    h0 = __floats2half2_rn(v.x, v.y);
                    h1 = __floats2half2_rn(v.z, v.w);
                    *(uint2*)(smem + bxm + bo) = make_uint2(*(uint32_t*)&h0, *(uint32_t*)&h1);
                }
                __syncthreads();

                const uint32_t abuf = sb + (uint32_t)(ck << 12);
                const uint32_t bbuf = sb + offB + (uint32_t)((ck & 1) << 12);
                uint32_t a[2][4], bf[8][2];
                #pragma unroll
                for (int mt = 0; mt < 2; mt++) {
                    int row = (mw << 5) + (mt << 4) + (lane & 15);
                    int kb  = (lane >> 4) << 4;
                    ldsm_x4(a[mt], abuf + swzA16((uint32_t)((row << 5) + kb)));
                }
                #pragma unroll
                for (int p = 0; p < 4; p++) {
                    int krow = lane & 15;
                    int ncol = (nw << 6) + (p << 4) + ((lane >> 4) << 3);
                    uint32_t rr[4];
                    ldsm_x4t(rr, bbuf + swzB((uint32_t)((krow << 8) + (ncol << 1))));
                    bf[2*p][0] = rr[0]; bf[2*p][1] = rr[1];
                    bf[2*p+1][0] = rr[2]; bf[2*p+1][1] = rr[3];
                }
                #pragma unroll
                for (int mt = 0; mt < 2; mt++)
                    #pragma unroll
                    for (int nt = 0; nt < 8; nt++)
                        mma16816(d[mt][nt], a[mt], bf[nt]);
            }
            epilogue_store(d, out, t >> 5, (t & 31) << 7, ch0, mw, nw, lane, false);
        }
    }
}

extern "C" void kernel_launch(void* const* d_in, const int* in_sizes, int n_in,
                              void* d_out, int out_size)
{
    const float* x = (const float*)d_in[0];
    const float* c = (const float*)d_in[1];
    prep_kernel<<<96, 256>>>((const float*)d_in[2], (const float*)d_in[3],
                             (const float*)d_in[4], (const float*)d_in[5],
                             (const float*)d_in[6], (const float*)d_in[7],
                             (const float*)d_in[8], (const float*)d_in[9],
                             (const float*)d_in[10], (const float*)d_in[11],
                             (const float*)d_in[12]);
    cudaFuncSetAttribute(main_kernel, cudaFuncAttributeMaxDynamicSharedMemorySize, SMEM_TOTAL);
    main_kernel<<<304, 256, SMEM_TOTAL>>>(x, c, (float*)d_out);
}

// round 13
// speedup vs baseline: 2.2708x; 1.2912x over previous
#include <cuda_runtime.h>
#include <cuda_fp16.h>
#include <cstdint>

#define EPS 1e-5f

__device__ __half g_Wh[384 * 256];
__device__ float g_bnsc[384];
__device__ float g_bnsh[384];

// ---- branch C (mblk 1,2: c-only, K32, 3-stage, convert-ahead) ----
#define C_A   0u        // A fp16: 3 bufs x 128 rows x 64B (swzA32) = 24 KB
#define C_B   24576u    // B fp16 c: 2 bufs x 32 rows x 256B (swzB) = 16 KB
#define C_S   40960u    // staging fp32 c: 3 bufs x 16 KB           = 48 KB
// ---- branch M (mblk 0: x+c, K32, 2-stage == R7) ----
#define M_A   0u        // 2 x 8 KB
#define M_BX  16384u    // 2 x 8 KB
#define M_BC  32768u    // 2 x 8 KB
#define M_SX  49152u    // 2 x 16 KB
#define M_SC  81920u    // 2 x 16 KB
#define SMEM_TOTAL 114688   // 112 KB -> 2 CTAs/SM

__device__ __forceinline__ uint32_t swzA32(uint32_t o) { return o ^ ((o >> 3) & 0x30); }
__device__ __forceinline__ uint32_t swzB(uint32_t o)   { return o ^ ((o >> 4) & 0x70); }

__device__ __forceinline__ uint32_t s2u(const void* p) {
    uint32_t a;
    asm("{ .reg .u64 t; cvta.to.shared.u64 t, %1; cvt.u32.u64 %0, t; }" : "=r"(a) : "l"(p));
    return a;
}
__device__ __forceinline__ void ldsm_x4(uint32_t* r, uint32_t a) {
    asm volatile("ldmatrix.sync.aligned.m8n8.x4.shared.b16 {%0,%1,%2,%3}, [%4];"
                 : "=r"(r[0]), "=r"(r[1]), "=r"(r[2]), "=r"(r[3]) : "r"(a));
}
__device__ __forceinline__ void ldsm_x4t(uint32_t* r, uint32_t a) {
    asm volatile("ldmatrix.sync.aligned.m8n8.x4.trans.shared.b16 {%0,%1,%2,%3}, [%4];"
                 : "=r"(r[0]), "=r"(r[1]), "=r"(r[2]), "=r"(r[3]) : "r"(a));
}
__device__ __forceinline__ void mma16816(float* d, const uint32_t* a, const uint32_t* b) {
    asm volatile("mma.sync.aligned.m16n8k16.row.col.f32.f16.f16.f32 "
                 "{%0,%1,%2,%3}, {%4,%5,%6,%7}, {%8,%9}, {%0,%1,%2,%3};"
                 : "+f"(d[0]), "+f"(d[1]), "+f"(d[2]), "+f"(d[3])
                 : "r"(a[0]), "r"(a[1]), "r"(a[2]), "r"(a[3]), "r"(b[0]), "r"(b[1]));
}
__device__ __forceinline__ void cpa16(uint32_t dst, const void* src) {
    asm volatile("cp.async.cg.shared.global [%0], [%1], 16;" :: "r"(dst), "l"(src));
}
__device__ __forceinline__ void cpa_commit() { asm volatile("cp.async.commit_group;"); }

// ---------------- prep: W fp32 -> fp16, fold BN ----------------
__global__ void prep_kernel(const float* __restrict__ Wq, const float* __restrict__ Wv,
                            const float* __restrict__ Wk,
                            const float* __restrict__ qg, const float* __restrict__ qb,
                            const float* __restrict__ qm, const float* __restrict__ qv,
                            const float* __restrict__ vg, const float* __restrict__ vb,
                            const float* __restrict__ vm, const float* __restrict__ vv)
{
    int idx = blockIdx.x * blockDim.x + threadIdx.x;
    int stride = gridDim.x * blockDim.x;
    for (int i = idx; i < 384 * 256; i += stride) {
        int r = i >> 8, k = i & 255;
        float w = (r < 64) ? Wq[(r << 8) | k]
                : (r < 320) ? Wv[((r - 64) << 8) | k]
                            : Wk[((r - 320) << 8) | k];
        g_Wh[i] = __float2half_rn(w);
    }
    if (idx < 384) {
        float sc = 1.f, sh = 0.f;
        if (idx < 320) {
            float g, b, m, v;
            if (idx < 64) { g = qg[idx]; b = qb[idx]; m = qm[idx]; v = qv[idx]; }
            else { g = vg[idx-64]; b = vb[idx-64]; m = vm[idx-64]; v = vv[idx-64]; }
            sc = g * rsqrtf(v + EPS);
            sh = b - m * sc;
        }
        g_bnsc[idx] = sc; g_bnsh[idx] = sh;
    }
}

// ---------------- shared epilogue ----------------
__device__ __forceinline__ void epilogue_store(
    float d[2][8][4], float* __restrict__ out,
    int b, int pxb, int ch0, int mw, int nw, int lane, bool isK)
{
    const int g = lane >> 2, cc = lane & 3;
    #pragma unroll
    for (int mt = 0; mt < 2; mt++) {
        const int chA = ch0 + (mw << 5) + (mt << 4) + g;
        float* oA = out + ((size_t)b * 384 + chA) * 4096 + pxb + (nw << 6);
        float* oB = oA + (size_t)8 * 4096;
        if (!isK) {
            float s0 = g_bnsc[chA],     h0 = g_bnsh[chA];
            float s1 = g_bnsc[chA + 8], h1 = g_bnsh[chA + 8];
            #pragma unroll
            for (int nt = 0; nt < 8; nt++) {
                int col = (nt << 3) + (cc << 1);
                *(float2*)(oA + col) = make_float2(fmaf(d[mt][nt][0], s0, h0),
                                                   fmaf(d[mt][nt][1], s0, h0));
                *(float2*)(oB + col) = make_float2(fmaf(d[mt][nt][2], s1, h1),
                                                   fmaf(d[mt][nt][3], s1, h1));
            }
        } else {
            float mx0 = -3.4e38f, mx1 = -3.4e38f;
            #pragma unroll
            for (int nt = 0; nt < 8; nt++) {
                mx0 = fmaxf(mx0, fmaxf(d[mt][nt][0], d[mt][nt][1]));
                mx1 = fmaxf(mx1, fmaxf(d[mt][nt][2], d[mt][nt][3]));
            }
            mx0 = fmaxf(mx0, __shfl_xor_sync(0xffffffffu, mx0, 1));
            mx0 = fmaxf(mx0, __shfl_xor_sync(0xffffffffu, mx0, 2));
            mx1 = fmaxf(mx1, __shfl_xor_sync(0xffffffffu, mx1, 1));
            mx1 = fmaxf(mx1, __shfl_xor_sync(0xffffffffu, mx1, 2));
            float s0 = 0.f, s1 = 0.f;
            #pragma unroll
            for (int nt = 0; nt < 8; nt++) {
                d[mt][nt][0] = __expf(d[mt][nt][0] - mx0); s0 += d[mt][nt][0];
                d[mt][nt][1] = __expf(d[mt][nt][1] - mx0); s0 += d[mt][nt][1];
                d[mt][nt][2] = __expf(d[mt][nt][2] - mx1); s1 += d[mt][nt][2];
                d[mt][nt][3] = __expf(d[mt][nt][3] - mx1); s1 += d[mt][nt][3];
            }
            s0 += __shfl_xor_sync(0xffffffffu, s0, 1);
            s0 += __shfl_xor_sync(0xffffffffu, s0, 2);
            s1 += __shfl_xor_sync(0xffffffffu, s1, 1);
            s1 += __shfl_xor_sync(0xffffffffu, s1, 2);
            float i0 = __frcp_rn(s0), i1 = __frcp_rn(s1);
            #pragma unroll
            for (int nt = 0; nt < 8; nt++) {
                int col = (nt << 3) + (cc << 1);
                *(float2*)(oA + col) = make_float2(d[mt][nt][0] * i0, d[mt][nt][1] * i0);
                *(float2*)(oB + col) = make_float2(d[mt][nt][2] * i1, d[mt][nt][3] * i1);
            }
        }
    }
}

// ---------------- main kernel ----------------
__global__ __launch_bounds__(256, 2)
void main_kernel(const float* __restrict__ x, const float* __restrict__ c,
                 float* __restrict__ out)
{
    extern __shared__ char smem[];
    const uint32_t sb = s2u(smem);
    const int tid = threadIdx.x, wid = tid >> 5, lane = tid & 31;
    const int mw = wid >> 1, nw = wid & 1;           // warp grid 4(M) x 2(N)
    const int bid = blockIdx.x;
    const int mblk = bid % 3;
    const int tile = bid / 3;
    const int b = tile >> 5, pxb = (tile & 31) << 7;
    const int ch0 = mblk << 7;

    float d[2][8][4];
    #pragma unroll
    for (int mt = 0; mt < 2; mt++)
        #pragma unroll
        for (int nt = 0; nt < 8; nt++)
            d[mt][nt][0] = d[mt][nt][1] = d[mt][nt][2] = d[mt][nt][3] = 0.f;

    if (mblk != 0) {
        // ===== branch C: c-only, K32, 3-stage, convert-ahead, 1 barrier/chunk =====
        auto issue = [&](int ck) {                    // 1 group: A(ck) + stg(ck)
            const int kc = ck << 5;
            const uint32_t asel = C_A + (uint32_t)(ck % 3) * 8192u;
            #pragma unroll
            for (int i = 0; i < 2; i++) {             // A: 512 granules
                int idx = tid + (i << 8);
                int r = idx >> 2, u = idx & 3;
                cpa16(sb + asel + swzA32((uint32_t)((r << 6) + (u << 4))),
                      g_Wh + ((ch0 + r) << 8) + kc + (u << 3));
            }
            const uint32_t ssel = C_S + (uint32_t)(ck % 3) * 16384u;
            #pragma unroll
            for (int i = 0; i < 4; i++) {             // stg c: 1024 granules
                int idx = tid + (i << 8);
                int kk = idx >> 5, p = idx & 31;
                cpa16(sb + ssel + (uint32_t)((kk << 9) + (p << 4)),
                      c + (size_t)((b << 8) + kc + kk) * 4096 + pxb + (p << 2));
            }
            cpa_commit();
        };
        auto convert = [&](int ck) {                  // reads only self-written granules
            const uint32_t ssel = C_S + (uint32_t)(ck % 3) * 16384u;
            const uint32_t bsel = C_B + (uint32_t)(ck & 1) * 8192u;
            #pragma unroll
            for (int i = 0; i < 4; i++) {
                int idx = tid + (i << 8);
                int kk = idx >> 5, p = idx & 31;
                float4 v = *(const float4*)(smem + ssel + (kk << 9) + (p << 4));
                __half2 h0 = __floats2half2_rn(v.x, v.y);
                __half2 h1 = __floats2half2_rn(v.z, v.w);
                *(uint2*)(smem + bsel + swzB((uint32_t)((kk << 8) + (p << 3)))) =
                    make_uint2(*(uint32_t*)&h0, *(uint32_t*)&h1);
            }
        };

        issue(0); issue(1);
        asm volatile("cp.async.wait_group 1;");
        convert(0);

        #pragma unroll
        for (int ck = 0; ck < 8; ck++) {
            __syncthreads();                          // publish A[ck], B16[ck]
            if (ck + 2 < 8) issue(ck + 2);
            if (ck + 1 < 8) {
                if (ck + 2 < 8) { asm volatile("cp.async.wait_group 1;"); }
                else            { asm volatile("cp.async.wait_group 0;"); }
                convert(ck + 1);                      // overlaps compute(ck) below
            }
            const uint32_t abuf = sb + C_A + (uint32_t)(ck % 3) * 8192u;
            const uint32_t bbuf = sb + C_B + (uint32_t)(ck & 1) * 8192u;
            #pragma unroll
            for (int ks = 0; ks < 2; ks++) {
                uint32_t a[2][4], bf[8][2];
                #pragma unroll
                for (int mt = 0; mt < 2; mt++) {
                    int row = (mw << 5) + (mt << 4) + (lane & 15);
                    int kb  = (ks << 5) + ((lane >> 4) << 4);
                    ldsm_x4(a[mt], abuf + swzA32((uint32_t)((row << 6) + kb)));
                }
                #pragma unroll
                for (int p = 0; p < 4; p++) {
                    int krow = (ks << 4) + (lane & 15);
                    int ncol = (nw << 6) + (p << 4) + ((lane >> 4) << 3);
                    uint32_t r[4];
                    ldsm_x4t(r, bbuf + swzB((uint32_t)((krow << 8) + (ncol << 1))));
                    bf[2*p][0] = r[0]; bf[2*p][1] = r[1];
                    bf[2*p+1][0] = r[2]; bf[2*p+1][1] = r[3];
                }
                #pragma unroll
                for (int mt = 0; mt < 2; mt++)
                    #pragma unroll
                    for (int nt = 0; nt < 8; nt++)
                        mma16816(d[mt][nt], a[mt], bf[nt]);
            }
        }
        epilogue_store(d, out, b, pxb, ch0, mw, nw, lane, (mblk == 2 && mw >= 2));
    } else {
        // ===== branch M: x+c, K32, 2-stage (R7 verbatim) =====
        const uint32_t offB = (mw < 2) ? M_BX : M_BC; // q uses x; v uses c
        auto issue = [&](int ck) {
            const int kc = ck << 5;
            const uint32_t sel13 = (uint32_t)((ck & 1) << 13);
            const uint32_t sel14 = (uint32_t)((ck & 1) << 14);
            #pragma unroll
            for (int i = 0; i < 2; i++) {
                int idx = tid + (i << 8);
                int r = idx >> 2, u = idx & 3;
                cpa16(sb + M_A + sel13 + swzA32((uint32_t)((r << 6) + (u << 4))),
                      g_Wh + (r << 8) + kc + (u << 3));
            }
            #pragma unroll
            for (int i = 0; i < 4; i++) {
                int idx = tid + (i << 8);
                int kk = idx >> 5, p = idx & 31;
                size_t go = (size_t)((b << 8) + kc + kk) * 4096 + pxb + (p << 2);
                uint32_t so = (uint32_t)((kk << 9) + (p << 4));
                cpa16(sb + M_SC + sel14 + so, c + go);
                cpa16(sb + M_SX + sel14 + so, x + go);
            }
            cpa_commit();
        };
        auto convert_one = [&](uint32_t stg, uint32_t dst16) {
            #pragma unroll
            for (int i = 0; i < 4; i++) {
                int idx = tid + (i << 8);
                int kk = idx >> 5, p = idx & 31;
                float4 v = *(const float4*)(smem + stg + (kk << 9) + (p << 4));
                __half2 h0 = __floats2half2_rn(v.x, v.y);
                __half2 h1 = __floats2half2_rn(v.z, v.w);
                *(uint2*)(smem + dst16 + swzB((uint32_t)((kk << 8) + (p << 3)))) =
                    make_uint2(*(uint32_t*)&h0, *(uint32_t*)&h1);
            }
        };

        issue(0);
        #pragma unroll
        for (int ck = 0; ck < 8; ck++) {
            asm volatile("cp.async.wait_group 0;");
            __syncthreads();
            if (ck < 7) issue(ck + 1);
            const uint32_t sel13 = (uint32_t)((ck & 1) << 13);
            const uint32_t sel14 = (uint32_t)((ck & 1) << 14);
            convert_one(M_SC + sel14, M_BC + sel13);
            convert_one(M_SX + sel14, M_BX + sel13);
            __syncthreads();

            const uint32_t abuf = sb + M_A + sel13;
            const uint32_t bbuf = sb + offB + sel13;
            #pragma unroll
            for (int ks = 0; ks < 2; ks++) {
                uint32_t a[2][4], bf[8][2];
                #pragma unroll
                for (int mt = 0; mt < 2; mt++) {
                    int row = (mw << 5) + (mt << 4) + (lane & 15);
                    int kb  = (ks << 5) + ((lane >> 4) << 4);
                    ldsm_x4(a[mt], abuf + swzA32((uint32_t)((row << 6) + kb)));
                }
                #pragma unroll
                for (int p = 0; p < 4; p++) {
                    int krow = (ks << 4) + (lane & 15);
                    int ncol = (nw << 6) + (p << 4) + ((lane >> 4) << 3);
                    uint32_t r[4];
                    ldsm_x4t(r, bbuf + swzB((uint32_t)((krow << 8) + (ncol << 1))));
                    bf[2*p][0] = r[0]; bf[2*p][1] = r[1];
                    bf[2*p+1][0] = r[2]; bf[2*p+1][1] = r[3];
                }
                #pragma unroll
                for (int mt = 0; mt < 2; mt++)
                    #pragma unroll
                    for (int nt = 0; nt < 8; nt++)
                        mma16816(d[mt][nt], a[mt], bf[nt]);
            }
        }
        epilogue_store(d, out, b, pxb, ch0, mw, nw, lane, false);
    }
}

extern "C" void kernel_launch(void* const* d_in, const int* in_sizes, int n_in,
                              void* d_out, int out_size)
{
    const float* x = (const float*)d_in[0];
    const float* c = (const float*)d_in[1];
    prep_kernel<<<96, 256>>>((const float*)d_in[2], (const float*)d_in[3],
                             (const float*)d_in[4], (const float*)d_in[5],
                             (const float*)d_in[6], (const float*)d_in[7],
                             (const float*)d_in[8], (const float*)d_in[9],
                             (const float*)d_in[10], (const float*)d_in[11],
                             (const float*)d_in[12]);
    cudaFuncSetAttribute(main_kernel, cudaFuncAttributeMaxDynamicSharedMemorySize, SMEM_TOTAL);
    main_kernel<<<3072, 256, SMEM_TOTAL>>>(x, c, (float*)d_out);
}